// round 2
// baseline (speedup 1.0000x reference)
#include <cuda_runtime.h>

#define LN 8      // layers
#define BN 64     // batch
#define TN 512    // time steps
#define HN 128    // hidden
#define ON 65     // output vocab
#define CPL 16    // CTAs per layer
#define UPC 8     // hidden units per CTA (HN / CPL)
#define GCOLS 32  // gate columns per CTA (UPC * 4)
#define NTHR 128
#define NCTA (LN * CPL)

// Inter-layer activation buffer, k-major: h of layer l at time t, [HN][BN].
// Full depth T => producers never wait on consumers (no backpressure, no deadlock).
__device__ float g_hbuf[LN][TN][HN][BN];
// Completion counters: g_cnt[l][t] reaches CPL when all 16 CTAs of layer l wrote h(t).
__device__ int g_cnt[LN][TN];

__device__ __forceinline__ float sig_(float x) {
    return __fdividef(1.f, 1.f + __expf(-x));
}
__device__ __forceinline__ float th_(float x) {
    // tanh(x) = 1 - 2/(exp(2x)+1); exact limits at +/-inf, ~1e-6 rel err
    return 1.f - __fdividef(2.f, __expf(2.f * x) + 1.f);
}

__global__ void __launch_bounds__(NTHR, 1) zero_cnt_kernel() {
    int i = blockIdx.x * blockDim.x + threadIdx.x;
    if (i < LN * TN) (&g_cnt[0][0])[i] = 0;
}

__global__ void __launch_bounds__(NTHR, 1) lstm_kernel(
    const int* __restrict__ x, const float* __restrict__ embed,
    const float* __restrict__ w_ih, const float* __restrict__ b_ih,
    const float* __restrict__ w_hh, const float* __restrict__ b_hh,
    float* __restrict__ out, int out_size)
{
    extern __shared__ float sm[];
    float* w_s  = sm;          // [2][128][32]: w_ih slice then w_hh slice, layout [k][lu*4+g]
    float* in_s = sm + 8192;   // [128][64] k-major input tile
    float* hp_s = sm + 16384;  // [128][64] k-major h_prev tile

    const int cta   = blockIdx.x;
    const int l     = cta >> 4;    // layer
    const int slice = cta & 15;    // which 8-unit slice of H
    const int tid   = threadIdx.x;
    const int warp  = tid >> 5;    // 0..3 -> local units {2w, 2w+1}
    const int lane  = tid & 31;    // rows lane and lane+32

    // ---- one-time: load weight slice into SMEM (stays for all 512 steps) ----
    for (int i = tid; i < HN * GCOLS; i += NTHR) {
        int k = i >> 5;
        int c = i & 31;            // c = lu*4 + g
        int lu = c >> 2, g = c & 3;
        int gc = g * HN + slice * UPC + lu;       // global gate column
        w_s[i]        = w_ih[(l * HN + k) * (4 * HN) + gc];
        w_s[4096 + i] = w_hh[(l * HN + k) * (4 * HN) + gc];
    }
    float bias[8];
#pragma unroll
    for (int c = 0; c < 8; c++) {
        int uu = c >> 2, g = c & 3;
        int gu = slice * UPC + warp * 2 + uu;
        bias[c] = b_ih[l * 4 * HN + g * HN + gu] + b_hh[l * 4 * HN + g * HN + gu];
    }
    float cst[2][2] = {{0.f, 0.f}, {0.f, 0.f}};   // cell state in registers
    __syncthreads();

    for (int t = 0; t < TN; t++) {
        // ---- stage layer input into in_s ----
        if (l == 0) {
            // embedding lookup, written k-major (warp lanes -> consecutive rows: no conflicts)
            int r  = tid & 63;
            int kh = (tid >> 6) << 6;
            int tok = x[r * TN + t];
            const float* er = embed + tok * HN;
#pragma unroll
            for (int k = kh; k < kh + 64; k += 4) {
                float4 v = *(const float4*)(er + k);
                in_s[(k + 0) * BN + r] = v.x;
                in_s[(k + 1) * BN + r] = v.y;
                in_s[(k + 2) * BN + r] = v.z;
                in_s[(k + 3) * BN + r] = v.w;
            }
        } else {
            if (tid == 0) {
                volatile int* cc = &g_cnt[l - 1][t];
                while (*cc < CPL) __nanosleep(40);
                __threadfence();
            }
            __syncthreads();
            const float4* src = (const float4*)&g_hbuf[l - 1][t][0][0];
            for (int i = tid; i < 2048; i += NTHR)
                ((float4*)in_s)[i] = __ldcg(src + i);   // L2 path: fresh data, no reuse
        }
        // ---- stage h_prev into hp_s ----
        if (t == 0) {
            for (int i = tid; i < 8192; i += NTHR) hp_s[i] = 0.f;
        } else {
            if (tid == 0) {
                volatile int* cc = &g_cnt[l][t - 1];
                while (*cc < CPL) __nanosleep(40);
                __threadfence();
            }
            __syncthreads();
            const float4* src = (const float4*)&g_hbuf[l][t - 1][0][0];
            for (int i = tid; i < 2048; i += NTHR)
                ((float4*)hp_s)[i] = __ldcg(src + i);
        }
        __syncthreads();

        // ---- gates = in @ Wih_slice + hprev @ Whh_slice + bias ----
        // per-thread tile: 2 rows x 2 units x 4 gates = 16 accumulators
        float acc[2][8];
#pragma unroll
        for (int c = 0; c < 8; c++) { acc[0][c] = bias[c]; acc[1][c] = bias[c]; }

        const float* wi = w_s + warp * 8;
        const float* wh = w_s + 4096 + warp * 8;
#pragma unroll 8
        for (int k = 0; k < HN; k++) {
            float a0 = in_s[k * BN + lane];
            float a1 = in_s[k * BN + lane + 32];
            float p0 = hp_s[k * BN + lane];
            float p1 = hp_s[k * BN + lane + 32];
            float4 wiA = *(const float4*)(wi + k * GCOLS);
            float4 wiB = *(const float4*)(wi + k * GCOLS + 4);
            float4 whA = *(const float4*)(wh + k * GCOLS);
            float4 whB = *(const float4*)(wh + k * GCOLS + 4);
            float wiv[8] = {wiA.x, wiA.y, wiA.z, wiA.w, wiB.x, wiB.y, wiB.z, wiB.w};
            float whv[8] = {whA.x, whA.y, whA.z, whA.w, whB.x, whB.y, whB.z, whB.w};
#pragma unroll
            for (int c = 0; c < 8; c++) {
                acc[0][c] += a0 * wiv[c];
                acc[0][c] += p0 * whv[c];
                acc[1][c] += a1 * wiv[c];
                acc[1][c] += p1 * whv[c];
            }
        }

        // ---- LSTM cell elementwise; publish h ----
#pragma unroll
        for (int rr = 0; rr < 2; rr++) {
            int r = lane + rr * 32;
#pragma unroll
            for (int uu = 0; uu < 2; uu++) {
                float iv = sig_(acc[rr][uu * 4 + 0]);
                float fv = sig_(acc[rr][uu * 4 + 1]);
                float gv = th_ (acc[rr][uu * 4 + 2]);
                float ov = sig_(acc[rr][uu * 4 + 3]);
                float c  = fv * cst[rr][uu] + iv * gv;
                cst[rr][uu] = c;
                float h = ov * th_(c);
                int gu = slice * UPC + warp * 2 + uu;
                g_hbuf[l][t][gu][r] = h;       // warp-coalesced (lanes -> consecutive r)
                if (t == TN - 1) {
                    int hidx = BN * TN * ON + (l * BN + r) * HN + gu;
                    int cidx = hidx + LN * BN * HN;
                    if (hidx < out_size) out[hidx] = h;
                    if (cidx < out_size) out[cidx] = c;
                }
            }
        }
        __threadfence();
        __syncthreads();
        if (tid == 0) atomicAdd(&g_cnt[l][t], 1);
    }
}

// outputs[b][t][o] = h7[t][b] . w_out[:,o] + b_out[o]; one CTA per t.
__global__ void __launch_bounds__(256, 1) proj_kernel(
    const float* __restrict__ w_out, const float* __restrict__ b_out,
    float* __restrict__ out, int out_size)
{
    extern __shared__ float sm[];
    float* h_s  = sm;          // [128][64] k-major (same layout as hbuf slice)
    float* w_sm = sm + 8192;   // [128][65]
    int t = blockIdx.x;
    int tid = threadIdx.x;
    const float4* src = (const float4*)&g_hbuf[LN - 1][t][0][0];
    for (int i = tid; i < 2048; i += 256) ((float4*)h_s)[i] = src[i];
    for (int i = tid; i < HN * ON; i += 256) w_sm[i] = w_out[i];
    __syncthreads();
    for (int idx = tid; idx < BN * ON; idx += 256) {
        int b = idx / ON, o = idx - b * ON;
        float s = b_out[o];
#pragma unroll 16
        for (int k = 0; k < HN; k++)
            s += h_s[k * BN + b] * w_sm[k * ON + o];
        int oi = (b * TN + t) * ON + o;
        if (oi < out_size) out[oi] = s;
    }
}

extern "C" void kernel_launch(void* const* d_in, const int* in_sizes, int n_in,
                              void* d_out, int out_size)
{
    const int*   x     = (const int*)d_in[0];
    const float* embed = (const float*)d_in[1];
    const float* w_ih  = (const float*)d_in[2];
    const float* b_ih  = (const float*)d_in[3];
    const float* w_hh  = (const float*)d_in[4];
    const float* b_hh  = (const float*)d_in[5];
    const float* w_out = (const float*)d_in[6];
    const float* b_out = (const float*)d_in[7];
    float* out = (float*)d_out;

    cudaFuncSetAttribute(lstm_kernel, cudaFuncAttributeMaxDynamicSharedMemorySize, 98304);
    cudaFuncSetAttribute(proj_kernel, cudaFuncAttributeMaxDynamicSharedMemorySize, 66048);

    zero_cnt_kernel<<<(LN * TN + NTHR - 1) / NTHR, NTHR>>>();
    lstm_kernel<<<NCTA, NTHR, 98304>>>(x, embed, w_ih, b_ih, w_hh, b_hh, out, out_size);
    proj_kernel<<<TN, 256, 66048>>>(w_out, b_out, out, out_size);
}